// round 14
// baseline (speedup 1.0000x reference)
#include <cuda_runtime.h>
#include <cstdint>

// Problem constants
#define NMAX 50000
#define EMAX 1000000
#define RNUM 8
#define BNUM 30
#define JTOT 576            // 8*64 relation cols + 64 self-loop cols
#define NSEG (NMAX * RNUM)  // 400000 (dst,relation) segments
#define SCHUNK 512
#define NBLK2 782           // ceil(400000/512)
#define NPAD2 (NBLK2 * SCHUNK)   // 400384

// ---------------- static device scratch ----------------
__device__ float g_Wtmp[JTOT * 64];              // Wcat [kk][o]
__device__ float g_Wcat2[JTOT * 64];             // Wcat @ W2 [kk][o]
__device__ float g_bias12[64];                   // bias1 @ W2
__device__ float g_z[(size_t)NMAX * JTOT];       // per-dst relation sums | self x
__device__ float g_g[(size_t)NMAX * 64];         // s * (z@Wcat2 + bias12)
__device__ int   g_deg_out[NMAX];
__device__ int   g_deg[NPAD2];                   // per-(dst,rel) counts, zero-padded
__device__ int   g_cursor[NSEG];
__device__ int   g_rowoff[NSEG + 1];
__device__ int   g_bsum[NBLK2];
__device__ int   g_boff[NBLK2];
__device__ int   g_csr[EMAX];                    // bare src index

// ---------------- f32x2 packed-FMA helpers ----------------
typedef unsigned long long ull;
__device__ __forceinline__ ull pack2(float lo, float hi) {
    ull r; asm("mov.b64 %0,{%1,%2};" : "=l"(r) : "f"(lo), "f"(hi)); return r;
}
__device__ __forceinline__ void unpack2(ull v, float& lo, float& hi) {
    asm("mov.b64 {%0,%1},%2;" : "=f"(lo), "=f"(hi) : "l"(v));
}
__device__ __forceinline__ void ffma2(ull& d, ull a, ull b) {
    asm("fma.rn.f32x2 %0,%1,%2,%0;" : "+l"(d) : "l"(a), "l"(b));
}

// ---------------- K0: zero counters ----------------
__global__ void zero_kernel(int n) {
    int i = blockIdx.x * blockDim.x + threadIdx.x;
    if (i < NPAD2) g_deg[i] = 0;
    if (i < NSEG) g_cursor[i] = 0;
    if (i < n) g_deg_out[i] = 0;
    if (i == 0) g_rowoff[0] = 0;
}

// ---------------- K1: Wcat (relation weights | loop weights) ----------------
__global__ void wcat_kernel(const float* __restrict__ basis,
                            const float* __restrict__ comp,
                            const float* __restrict__ loopw) {
    int idx = blockIdx.x * blockDim.x + threadIdx.x;
    if (idx >= JTOT * 64) return;
    int o = idx & 63;
    int kk = idx >> 6;
    if (kk < RNUM * 64) {
        int r = kk >> 6, i = kk & 63;
        float s = 0.f;
#pragma unroll
        for (int b = 0; b < BNUM; b++)
            s += comp[r * BNUM + b] * basis[(b * 64 + i) * 64 + o];
        g_Wtmp[kk * 64 + o] = s;
    } else {
        int i = kk - RNUM * 64;
        g_Wtmp[kk * 64 + o] = loopw[i * 64 + o];
    }
}

// ---------------- K1b: Wcat2 = Wcat @ W2, bias12 = bias1 @ W2 ----------------
__global__ void wcat2_kernel(const float* __restrict__ w2,
                             const float* __restrict__ bias1) {
    int idx = blockIdx.x * blockDim.x + threadIdx.x;
    if (idx >= JTOT * 64) return;
    int o = idx & 63;
    int kk = idx >> 6;
    float s = 0.f;
#pragma unroll 8
    for (int k = 0; k < 64; k++)
        s += g_Wtmp[kk * 64 + k] * w2[k * 64 + o];
    g_Wcat2[kk * 64 + o] = s;
    if (idx < 64) {
        float b = 0.f;
#pragma unroll 8
        for (int k = 0; k < 64; k++)
            b += bias1[k] * w2[k * 64 + idx];
        g_bias12[idx] = b;
    }
}

// ---------------- K2: counts per (dst,rel) segment + out-degree ----------------
__global__ void deg_kernel(const int* __restrict__ ei,
                           const int* __restrict__ et, int e) {
    int i = blockIdx.x * blockDim.x + threadIdx.x;
    if (i < e) {
        atomicAdd(&g_deg_out[ei[i]], 1);
        atomicAdd(&g_deg[ei[e + i] * RNUM + et[i]], 1);
    }
}

// ---------------- K3a: per-block sums ----------------
__global__ void scan1_kernel() {
    __shared__ int ws[8];
    int b = blockIdx.x, tid = threadIdx.x, lane = tid & 31, wid = tid >> 5;
    int2 v = *(const int2*)&g_deg[b * SCHUNK + tid * 2];
    int s = v.x + v.y;
#pragma unroll
    for (int off = 16; off >= 1; off >>= 1)
        s += __shfl_down_sync(0xFFFFFFFFu, s, off);
    if (lane == 0) ws[wid] = s;
    __syncthreads();
    if (tid == 0) {
        int t = 0;
#pragma unroll
        for (int j = 0; j < 8; j++) t += ws[j];
        g_bsum[b] = t;
    }
}

// ---------------- K3b: exclusive scan of block sums ----------------
__global__ void scan2_kernel() {
    __shared__ int wsum[32];
    int tid = threadIdx.x, lane = tid & 31, wid = tid >> 5;
    int v = (tid < NBLK2) ? g_bsum[tid] : 0;
    int sc = v;
#pragma unroll
    for (int off = 1; off < 32; off <<= 1) {
        int t = __shfl_up_sync(0xFFFFFFFFu, sc, off);
        if (lane >= off) sc += t;
    }
    if (lane == 31) wsum[wid] = sc;
    __syncthreads();
    if (wid == 0) {
        int w = wsum[lane];
        int s2 = w;
#pragma unroll
        for (int off = 1; off < 32; off <<= 1) {
            int t = __shfl_up_sync(0xFFFFFFFFu, s2, off);
            if (lane >= off) s2 += t;
        }
        wsum[lane] = s2 - w;
    }
    __syncthreads();
    if (tid < NBLK2) g_boff[tid] = sc - v + wsum[wid];
}

// ---------------- K3c: per-block scan + global offset -> rowoff ----------------
__global__ void scan3_kernel() {
    __shared__ int ws[8];
    __shared__ int wx[8];
    int b = blockIdx.x, tid = threadIdx.x, lane = tid & 31, wid = tid >> 5;
    int i0 = b * SCHUNK + tid * 2;
    int2 v = *(const int2*)&g_deg[i0];
    int ps = v.x + v.y;
    int sc = ps;
#pragma unroll
    for (int off = 1; off < 32; off <<= 1) {
        int t = __shfl_up_sync(0xFFFFFFFFu, sc, off);
        if (lane >= off) sc += t;
    }
    if (lane == 31) ws[wid] = sc;
    __syncthreads();
    if (tid == 0) {
        int run = 0;
#pragma unroll
        for (int j = 0; j < 8; j++) { wx[j] = run; run += ws[j]; }
    }
    __syncthreads();
    int excl = (sc - ps) + wx[wid] + g_boff[b];
    int r1 = excl + v.x;
    int r2 = r1 + v.y;
    if (i0 < NSEG)     g_rowoff[i0 + 1] = r1;
    if (i0 + 1 < NSEG) g_rowoff[i0 + 2] = r2;
}

// ---------------- K4: fill CSR (sorted by (dst, rel)) ----------------
__global__ void fill_kernel(const int* __restrict__ ei,
                            const int* __restrict__ et, int e) {
    int i = blockIdx.x * blockDim.x + threadIdx.x;
    if (i < e) {
        int seg = ei[e + i] * RNUM + et[i];
        int pos = g_rowoff[seg] + atomicAdd(&g_cursor[seg], 1);
        g_csr[pos] = ei[i];
    }
}

// ---------------- K5: aggz — streaming flush-on-boundary, float2 lanes, batch-4 MLP ----------------
__global__ void aggz_kernel(const float* __restrict__ x, int n) {
    int gw   = (blockIdx.x * blockDim.x + threadIdx.x) >> 5;
    int lane = threadIdx.x & 31;
    if (gw >= n) return;
    int base = gw * RNUM;
    int bval = (lane <= RNUM) ? g_rowoff[base + lane] : 0;   // lanes 0..8 hold boundaries
    int e    = __shfl_sync(0xFFFFFFFFu, bval, 0);
    int end8 = __shfl_sync(0xFFFFFFFFu, bval, RNUM);
    const float2* x2 = (const float2*)x;
    float2* zr = (float2*)&g_z[(size_t)gw * JTOT];

    float2 acc = make_float2(0.f, 0.f);
    int r = 0;
    int segEnd = __shfl_sync(0xFFFFFFFFu, bval, 1);

    while (e < end8) {
        int m = end8 - e; if (m > 4) m = 4;
        int p0 = 0, p1 = 0, p2 = 0, p3 = 0;
        p0 = g_csr[e];
        if (m > 1) p1 = g_csr[e + 1];
        if (m > 2) p2 = g_csr[e + 2];
        if (m > 3) p3 = g_csr[e + 3];
        float2 v0, v1, v2, v3;
        v0 = x2[(size_t)p0 * 32 + lane];
        if (m > 1) v1 = x2[(size_t)p1 * 32 + lane];
        if (m > 2) v2 = x2[(size_t)p2 * 32 + lane];
        if (m > 3) v3 = x2[(size_t)p3 * 32 + lane];
#pragma unroll
        for (int j = 0; j < 4; j++) {
            if (j < m) {
                int idx = e + j;
                while (idx >= segEnd) {          // flush completed segments (incl. empties)
                    zr[r * 32 + lane] = acc;
                    acc = make_float2(0.f, 0.f);
                    r++;
                    segEnd = __shfl_sync(0xFFFFFFFFu, bval, r + 1);
                }
                float2 v = (j == 0) ? v0 : (j == 1) ? v1 : (j == 2) ? v2 : v3;
                acc.x += v.x;
                acc.y += v.y;
            }
        }
        e += m;
    }
    // flush remaining segments (current + trailing empties)
    while (r < RNUM) {
        zr[r * 32 + lane] = acc;
        acc = make_float2(0.f, 0.f);
        r++;
    }
    // self-loop columns
    zr[256 + lane] = x2[(size_t)gw * 32 + lane];
}

// ---------------- K6: GEMM: g = rsqrt(deg_out) * (z @ Wcat2 + bias12) ----------------
__global__ __launch_bounds__(256) void gemm_kernel(int M) {
    __shared__ float shA[32][132];   // [k][m], padded
    __shared__ float shB[32][64];

    int tid = threadIdx.x;
    int tx = tid & 15, ty = tid >> 4;
    int mBase = blockIdx.x * 128;
    int rowL = tid >> 1, half = tid & 1;
    int gr = mBase + rowL;

    ull acc[4][4] = {};
    for (int k0 = 0; k0 < JTOT; k0 += 32) {
        __syncthreads();
#pragma unroll
        for (int q = 0; q < 4; q++) {
            int kk = half * 16 + q * 4;
            float4 v = make_float4(0.f, 0.f, 0.f, 0.f);
            if (gr < M) v = *(const float4*)&g_z[(size_t)gr * JTOT + k0 + kk];
            shA[kk][rowL] = v.x; shA[kk + 1][rowL] = v.y;
            shA[kk + 2][rowL] = v.z; shA[kk + 3][rowL] = v.w;
        }
        {
            int f = tid * 8, kr = f >> 6, c = f & 63;
            *(float4*)&shB[kr][c]     = *(const float4*)&g_Wcat2[(size_t)(k0 + kr) * 64 + c];
            *(float4*)&shB[kr][c + 4] = *(const float4*)&g_Wcat2[(size_t)(k0 + kr) * 64 + c + 4];
        }
        __syncthreads();
#pragma unroll
        for (int k = 0; k < 32; k++) {
            float4 b = *(const float4*)&shB[k][tx * 4];
            ull bd0 = pack2(b.x, b.x), bd1 = pack2(b.y, b.y);
            ull bd2 = pack2(b.z, b.z), bd3 = pack2(b.w, b.w);
#pragma unroll
            for (int i = 0; i < 4; i++) {
                ull a = *(const ull*)&shA[k][ty * 8 + 2 * i];
                ffma2(acc[i][0], a, bd0);
                ffma2(acc[i][1], a, bd1);
                ffma2(acc[i][2], a, bd2);
                ffma2(acc[i][3], a, bd3);
            }
        }
    }
    float4 bv = *(const float4*)&g_bias12[tx * 4];
#pragma unroll
    for (int i = 0; i < 4; i++) {
        float lo[4], hi[4];
#pragma unroll
        for (int j = 0; j < 4; j++) unpack2(acc[i][j], lo[j], hi[j]);
        int g0 = mBase + ty * 8 + 2 * i, g1 = g0 + 1;
        if (g0 < M) {
            float s = rsqrtf((float)max(g_deg_out[g0], 1));
            *(float4*)&g_g[(size_t)g0 * 64 + tx * 4] =
                make_float4((lo[0] + bv.x) * s, (lo[1] + bv.y) * s,
                            (lo[2] + bv.z) * s, (lo[3] + bv.w) * s);
        }
        if (g1 < M) {
            float s = rsqrtf((float)max(g_deg_out[g1], 1));
            *(float4*)&g_g[(size_t)g1 * 64 + tx * 4] =
                make_float4((hi[0] + bv.x) * s, (hi[1] + bv.y) * s,
                            (hi[2] + bv.z) * s, (hi[3] + bv.w) * s);
        }
    }
}

// ---------------- K7: agg3 — float2 lanes, batch-4 ----------------
__global__ void agg3_kernel(const float* __restrict__ bias2,
                            float* __restrict__ out, int n) {
    int gw   = (blockIdx.x * blockDim.x + threadIdx.x) >> 5;
    int lane = threadIdx.x & 31;
    if (gw >= n) return;
    int beg = g_rowoff[gw * RNUM], end = g_rowoff[gw * RNUM + RNUM];
    const float2* g2 = (const float2*)g_g;

    float2 a = make_float2(0.f, 0.f);
    int e = beg;
    for (; e + 3 < end; e += 4) {
        int p0 = g_csr[e], p1 = g_csr[e + 1], p2 = g_csr[e + 2], p3 = g_csr[e + 3];
        float2 v0 = g2[(size_t)p0 * 32 + lane];
        float2 v1 = g2[(size_t)p1 * 32 + lane];
        float2 v2 = g2[(size_t)p2 * 32 + lane];
        float2 v3 = g2[(size_t)p3 * 32 + lane];
        a.x += (v0.x + v1.x) + (v2.x + v3.x);
        a.y += (v0.y + v1.y) + (v2.y + v3.y);
    }
    for (; e < end; e++) {
        float2 v = g2[(size_t)g_csr[e] * 32 + lane];
        a.x += v.x;
        a.y += v.y;
    }
    float sc = rsqrtf((float)max(end - beg, 1));
    float2 b2 = *(const float2*)&bias2[lane * 2];
    ((float2*)out)[(size_t)gw * 32 + lane] =
        make_float2(a.x * sc + b2.x, a.y * sc + b2.y);
}

// ---------------- launch ----------------
extern "C" void kernel_launch(void* const* d_in, const int* in_sizes, int n_in,
                              void* d_out, int out_size) {
    const float* x     = (const float*)d_in[0];
    const int*   ei    = (const int*)d_in[1];   // int32 (JAX x64 disabled)
    const int*   et    = (const int*)d_in[3];   // int32
    const float* basis = (const float*)d_in[4];
    const float* comp  = (const float*)d_in[5];
    const float* loopw = (const float*)d_in[6];
    const float* bias1 = (const float*)d_in[7];
    const float* w2    = (const float*)d_in[8];
    const float* bias2 = (const float*)d_in[9];
    float* out = (float*)d_out;

    int n = in_sizes[0] / 64;    // 50000
    int e = in_sizes[1] / 2;     // 1000000

    zero_kernel<<<(NPAD2 + 255) / 256, 256>>>(n);
    wcat_kernel<<<(JTOT * 64 + 255) / 256, 256>>>(basis, comp, loopw);
    wcat2_kernel<<<(JTOT * 64 + 255) / 256, 256>>>(w2, bias1);
    deg_kernel<<<(e + 255) / 256, 256>>>(ei, et, e);
    scan1_kernel<<<NBLK2, 256>>>();
    scan2_kernel<<<1, 1024>>>();
    scan3_kernel<<<NBLK2, 256>>>();
    fill_kernel<<<(e + 255) / 256, 256>>>(ei, et, e);

    aggz_kernel<<<(n * 32 + 255) / 256, 256>>>(x, n);
    gemm_kernel<<<(n + 127) / 128, 256>>>(n);
    agg3_kernel<<<(n * 32 + 255) / 256, 256>>>(bias2, out, n);
}